// round 1
// baseline (speedup 1.0000x reference)
#include <cuda_runtime.h>

#define BATCH 4
#define NHEAD 4
#define SEQ   4096
#define HD    64
#define CH    256
#define NTOK  (BATCH * SEQ)   // 16384

// Scratch (device globals: allocation-free per harness rules)
__device__ float g_q[BATCH * NHEAD * SEQ * HD];
__device__ float g_k[BATCH * NHEAD * SEQ * HD];
__device__ float g_v[BATCH * NHEAD * SEQ * HD];
__device__ float g_o[BATCH * NHEAD * SEQ * HD];

// ---------------------------------------------------------------------------
// Kernel 1: QKV projection.  X[16384,256] @ W[256,768] + b  -> q/k/v scratch
// Block tile 64x64, 256 threads, 4x4 per-thread register tile, BK=16.
// Q is pre-scaled by hd^-0.5.
// ---------------------------------------------------------------------------
__global__ __launch_bounds__(256)
void qkv_kernel(const float* __restrict__ x, const float* __restrict__ w,
                const float* __restrict__ bias) {
    __shared__ float Xs[64][16];
    __shared__ float Ws[16][64];
    const int t  = threadIdx.x;
    const int tx = t & 15, ty = t >> 4;
    const int row0 = blockIdx.y * 64;
    const int col0 = blockIdx.x * 64;

    float acc[4][4] = {};

    for (int k0 = 0; k0 < CH; k0 += 16) {
        {   // cooperative loads: one float4 per thread per tile
            int r  = t >> 2, k4 = (t & 3) << 2;
            *(float4*)&Xs[r][k4] = *(const float4*)(x + (size_t)(row0 + r) * CH + k0 + k4);
            int kk = t >> 4, c4 = (t & 15) << 2;
            *(float4*)&Ws[kk][c4] = *(const float4*)(w + (size_t)(k0 + kk) * (3 * CH) + col0 + c4);
        }
        __syncthreads();
        #pragma unroll
        for (int k4 = 0; k4 < 16; k4 += 4) {
            float4 xv[4], wv[4];
            #pragma unroll
            for (int i = 0; i < 4; i++) xv[i] = *(float4*)&Xs[ty * 4 + i][k4];
            #pragma unroll
            for (int kk = 0; kk < 4; kk++) wv[kk] = *(float4*)&Ws[k4 + kk][tx * 4];
            #pragma unroll
            for (int i = 0; i < 4; i++) {
                acc[i][0] += xv[i].x * wv[0].x + xv[i].y * wv[1].x + xv[i].z * wv[2].x + xv[i].w * wv[3].x;
                acc[i][1] += xv[i].x * wv[0].y + xv[i].y * wv[1].y + xv[i].z * wv[2].y + xv[i].w * wv[3].y;
                acc[i][2] += xv[i].x * wv[0].z + xv[i].y * wv[1].z + xv[i].z * wv[2].z + xv[i].w * wv[3].z;
                acc[i][3] += xv[i].x * wv[0].w + xv[i].y * wv[1].w + xv[i].z * wv[2].w + xv[i].w * wv[3].w;
            }
        }
        __syncthreads();
    }

    // Epilogue: route this 64-wide column block to q/k/v (block maps to exactly
    // one (which, head) since tiles are 64-aligned and hd == 64).
    const int which = col0 >> 8;            // 0=q 1=k 2=v
    const int head  = (col0 & 255) >> 6;
    float* dst = (which == 0) ? g_q : (which == 1) ? g_k : g_v;
    const float qscale = (which == 0) ? 0.125f : 1.0f;   // hd^-0.5 = 64^-0.5

    #pragma unroll
    for (int i = 0; i < 4; i++) {
        int rowg = row0 + ty * 4 + i;
        int b = rowg >> 12;
        int n = rowg & (SEQ - 1);
        float4 v;
        v.x = (acc[i][0] + bias[col0 + tx * 4 + 0]) * qscale;
        v.y = (acc[i][1] + bias[col0 + tx * 4 + 1]) * qscale;
        v.z = (acc[i][2] + bias[col0 + tx * 4 + 2]) * qscale;
        v.w = (acc[i][3] + bias[col0 + tx * 4 + 3]) * qscale;
        *(float4*)(dst + ((size_t)(b * NHEAD + head) * SEQ + n) * HD + (tx << 2)) = v;
    }
}

// ---------------------------------------------------------------------------
// Kernel 2: flash attention, fp32.
// One block per (bh, 64-query tile). 256 threads, 4x4 register tiles for both
// S = Q K^T and O += P V. Online softmax state (m, l) replicated per row-group
// via 16-lane shuffles. Smem rows padded to 68 floats -> conflict-free float4.
// ---------------------------------------------------------------------------
#define SMS 68
#define ATT_SMEM (4 * 64 * SMS * sizeof(float))   // Qs, Ks, Vs, Ps

__global__ __launch_bounds__(256)
void attn_kernel() {
    extern __shared__ float sm[];
    float* Qs = sm;
    float* Ks = sm + 64 * SMS;
    float* Vs = sm + 2 * 64 * SMS;
    float* Ps = sm + 3 * 64 * SMS;

    const int t  = threadIdx.x;
    const int tx = t & 15, ty = t >> 4;
    const int bh = blockIdx.y;
    const int q0 = blockIdx.x << 6;

    const float* Qg = g_q + (size_t)bh * SEQ * HD + (size_t)q0 * HD;
    const float* Kg = g_k + (size_t)bh * SEQ * HD;
    const float* Vg = g_v + (size_t)bh * SEQ * HD;

    // Load Q tile (already scaled)
    #pragma unroll
    for (int i = 0; i < 4; i++) {
        int idx = t + 256 * i;
        int r = idx >> 4, c4 = (idx & 15) << 2;
        *(float4*)(Qs + r * SMS + c4) = *(const float4*)(Qg + r * HD + c4);
    }

    float m[4], l[4], acc[4][4];
    #pragma unroll
    for (int i = 0; i < 4; i++) {
        m[i] = -1e30f; l[i] = 0.0f;
        #pragma unroll
        for (int j = 0; j < 4; j++) acc[i][j] = 0.0f;
    }

    for (int kt = 0; kt < SEQ / 64; kt++) {
        __syncthreads();   // prior iter done reading Ks/Vs/Ps
        const float* Kt = Kg + (size_t)kt * 64 * HD;
        const float* Vt = Vg + (size_t)kt * 64 * HD;
        #pragma unroll
        for (int i = 0; i < 4; i++) {
            int idx = t + 256 * i;
            int r = idx >> 4, c4 = (idx & 15) << 2;
            *(float4*)(Ks + r * SMS + c4) = *(const float4*)(Kt + r * HD + c4);
            *(float4*)(Vs + r * SMS + c4) = *(const float4*)(Vt + r * HD + c4);
        }
        __syncthreads();

        // GEMM1: s[i][j] = sum_d Q[ty4+i][d] * K[tx4+j][d]
        float s[4][4];
        #pragma unroll
        for (int i = 0; i < 4; i++)
            #pragma unroll
            for (int j = 0; j < 4; j++) s[i][j] = 0.0f;

        #pragma unroll 4
        for (int d = 0; d < HD; d += 4) {
            float4 qv[4], kv[4];
            #pragma unroll
            for (int i = 0; i < 4; i++) qv[i] = *(float4*)(Qs + (ty * 4 + i) * SMS + d);
            #pragma unroll
            for (int j = 0; j < 4; j++) kv[j] = *(float4*)(Ks + (tx * 4 + j) * SMS + d);
            #pragma unroll
            for (int i = 0; i < 4; i++)
                #pragma unroll
                for (int j = 0; j < 4; j++)
                    s[i][j] += qv[i].x * kv[j].x + qv[i].y * kv[j].y
                             + qv[i].z * kv[j].z + qv[i].w * kv[j].w;
        }

        // Online softmax. Row groups live in 16-lane warp halves (xor 1..8 safe).
        #pragma unroll
        for (int i = 0; i < 4; i++) {
            float mx = fmaxf(fmaxf(s[i][0], s[i][1]), fmaxf(s[i][2], s[i][3]));
            #pragma unroll
            for (int o = 8; o; o >>= 1) mx = fmaxf(mx, __shfl_xor_sync(0xffffffffu, mx, o));
            float mnew  = fmaxf(m[i], mx);
            float alpha = __expf(m[i] - mnew);
            float rs = 0.0f;
            #pragma unroll
            for (int j = 0; j < 4; j++) { s[i][j] = __expf(s[i][j] - mnew); rs += s[i][j]; }
            #pragma unroll
            for (int o = 8; o; o >>= 1) rs += __shfl_xor_sync(0xffffffffu, rs, o);
            m[i] = mnew;
            l[i] = l[i] * alpha + rs;
            #pragma unroll
            for (int j = 0; j < 4; j++) acc[i][j] *= alpha;
        }

        // Stage P
        #pragma unroll
        for (int i = 0; i < 4; i++)
            *(float4*)(Ps + (ty * 4 + i) * SMS + (tx << 2)) =
                make_float4(s[i][0], s[i][1], s[i][2], s[i][3]);
        __syncthreads();

        // GEMM2: acc[i][j] += sum_k P[ty4+i][k] * V[k][tx4+j]
        #pragma unroll 4
        for (int k = 0; k < 64; k += 4) {
            float4 pv[4], vv[4];
            #pragma unroll
            for (int i = 0; i < 4; i++)  pv[i]  = *(float4*)(Ps + (ty * 4 + i) * SMS + k);
            #pragma unroll
            for (int kk = 0; kk < 4; kk++) vv[kk] = *(float4*)(Vs + (k + kk) * SMS + (tx << 2));
            #pragma unroll
            for (int i = 0; i < 4; i++) {
                acc[i][0] += pv[i].x * vv[0].x + pv[i].y * vv[1].x + pv[i].z * vv[2].x + pv[i].w * vv[3].x;
                acc[i][1] += pv[i].x * vv[0].y + pv[i].y * vv[1].y + pv[i].z * vv[2].y + pv[i].w * vv[3].y;
                acc[i][2] += pv[i].x * vv[0].z + pv[i].y * vv[1].z + pv[i].z * vv[2].z + pv[i].w * vv[3].z;
                acc[i][3] += pv[i].x * vv[0].w + pv[i].y * vv[1].w + pv[i].z * vv[2].w + pv[i].w * vv[3].w;
            }
        }
    }

    float* Og = g_o + (size_t)bh * SEQ * HD + (size_t)q0 * HD;
    #pragma unroll
    for (int i = 0; i < 4; i++) {
        float inv = 1.0f / l[i];
        float4 v = make_float4(acc[i][0] * inv, acc[i][1] * inv,
                               acc[i][2] * inv, acc[i][3] * inv);
        *(float4*)(Og + (ty * 4 + i) * HD + (tx << 2)) = v;
    }
}

// ---------------------------------------------------------------------------
// Kernel 3: output projection.  O[16384,256] @ W_out[256,256] + b_out -> out.
// O scratch is [b,h,n,d]; channel c = h*64+d, each BK=16 chunk stays within
// one head so loads remain contiguous float4s.
// ---------------------------------------------------------------------------
__global__ __launch_bounds__(256)
void proj_kernel(const float* __restrict__ w, const float* __restrict__ bias,
                 float* __restrict__ out) {
    __shared__ float Xs[64][16];
    __shared__ float Ws[16][64];
    const int t  = threadIdx.x;
    const int tx = t & 15, ty = t >> 4;
    const int row0 = blockIdx.y * 64;
    const int col0 = blockIdx.x * 64;
    const int b  = row0 >> 12;
    const int n0 = row0 & (SEQ - 1);

    float acc[4][4] = {};

    for (int k0 = 0; k0 < CH; k0 += 16) {
        const int h  = k0 >> 6;
        const int d0 = k0 & 63;
        {
            int r = t >> 2, k4 = (t & 3) << 2;
            const float* src = g_o + ((size_t)(b * NHEAD + h) * SEQ + n0 + r) * HD + d0 + k4;
            *(float4*)&Xs[r][k4] = *(const float4*)src;
            int kk = t >> 4, c4 = (t & 15) << 2;
            *(float4*)&Ws[kk][c4] = *(const float4*)(w + (size_t)(k0 + kk) * CH + col0 + c4);
        }
        __syncthreads();
        #pragma unroll
        for (int k4 = 0; k4 < 16; k4 += 4) {
            float4 xv[4], wv[4];
            #pragma unroll
            for (int i = 0; i < 4; i++) xv[i] = *(float4*)&Xs[ty * 4 + i][k4];
            #pragma unroll
            for (int kk = 0; kk < 4; kk++) wv[kk] = *(float4*)&Ws[k4 + kk][tx * 4];
            #pragma unroll
            for (int i = 0; i < 4; i++) {
                acc[i][0] += xv[i].x * wv[0].x + xv[i].y * wv[1].x + xv[i].z * wv[2].x + xv[i].w * wv[3].x;
                acc[i][1] += xv[i].x * wv[0].y + xv[i].y * wv[1].y + xv[i].z * wv[2].y + xv[i].w * wv[3].y;
                acc[i][2] += xv[i].x * wv[0].z + xv[i].y * wv[1].z + xv[i].z * wv[2].z + xv[i].w * wv[3].z;
                acc[i][3] += xv[i].x * wv[0].w + xv[i].y * wv[1].w + xv[i].z * wv[2].w + xv[i].w * wv[3].w;
            }
        }
        __syncthreads();
    }

    #pragma unroll
    for (int i = 0; i < 4; i++) {
        float4 v;
        v.x = acc[i][0] + bias[col0 + tx * 4 + 0];
        v.y = acc[i][1] + bias[col0 + tx * 4 + 1];
        v.z = acc[i][2] + bias[col0 + tx * 4 + 2];
        v.w = acc[i][3] + bias[col0 + tx * 4 + 3];
        *(float4*)(out + (size_t)(row0 + ty * 4 + i) * CH + col0 + (tx << 2)) = v;
    }
}

// ---------------------------------------------------------------------------
extern "C" void kernel_launch(void* const* d_in, const int* in_sizes, int n_in,
                              void* d_out, int out_size) {
    const float* x     = (const float*)d_in[0];
    const float* w_qkv = (const float*)d_in[1];
    const float* b_qkv = (const float*)d_in[2];
    const float* w_out = (const float*)d_in[3];
    const float* b_out = (const float*)d_in[4];
    float* out = (float*)d_out;

    qkv_kernel<<<dim3(12, NTOK / 64), 256>>>(x, w_qkv, b_qkv);

    cudaFuncSetAttribute(attn_kernel,
                         cudaFuncAttributeMaxDynamicSharedMemorySize,
                         (int)ATT_SMEM);
    attn_kernel<<<dim3(SEQ / 64, BATCH * NHEAD), 256, ATT_SMEM>>>();

    proj_kernel<<<dim3(CH / 64, NTOK / 64), 256>>>(w_out, b_out, out);
}

// round 2
// speedup vs baseline: 3.7865x; 3.7865x over previous
#include <cuda_runtime.h>

#define BATCH 4
#define NHEAD 4
#define SEQ   4096
#define HD    64
#define CH    256
#define NTOK  (BATCH * SEQ)   // 16384

// Scratch (device globals: allocation-free per harness rules)
__device__ float g_q[BATCH * NHEAD * SEQ * HD];
__device__ float g_k[BATCH * NHEAD * SEQ * HD];
__device__ float g_v[BATCH * NHEAD * SEQ * HD];
__device__ float g_o[BATCH * NHEAD * SEQ * HD];

// ---------------------------------------------------------------------------
// helpers
// ---------------------------------------------------------------------------
__device__ __forceinline__ unsigned f2tf32(float x) {
    unsigned r;
    asm("cvt.rna.tf32.f32 %0, %1;" : "=r"(r) : "f"(x));
    return r;
}

__device__ __forceinline__ void mma_tf32(float& c0, float& c1, float& c2, float& c3,
                                         unsigned a0, unsigned a1, unsigned a2, unsigned a3,
                                         unsigned b0, unsigned b1) {
    asm volatile(
        "mma.sync.aligned.m16n8k8.row.col.f32.tf32.tf32.f32 "
        "{%0,%1,%2,%3},{%4,%5,%6,%7},{%8,%9},{%0,%1,%2,%3};\n"
        : "+f"(c0), "+f"(c1), "+f"(c2), "+f"(c3)
        : "r"(a0), "r"(a1), "r"(a2), "r"(a3), "r"(b0), "r"(b1));
}

// ---------------------------------------------------------------------------
// Kernel 1: QKV projection.  X[16384,256] @ W[256,768] + b  -> q/k/v scratch
// Q is pre-scaled by hd^-0.5. q/k/v are stored tf32-rounded (attention
// consumes them as tf32 mma operands).
// ---------------------------------------------------------------------------
__global__ __launch_bounds__(256)
void qkv_kernel(const float* __restrict__ x, const float* __restrict__ w,
                const float* __restrict__ bias) {
    __shared__ float Xs[64][16];
    __shared__ float Ws[16][64];
    const int t  = threadIdx.x;
    const int tx = t & 15, ty = t >> 4;
    const int row0 = blockIdx.y * 64;
    const int col0 = blockIdx.x * 64;

    float acc[4][4] = {};

    for (int k0 = 0; k0 < CH; k0 += 16) {
        {
            int r  = t >> 2, k4 = (t & 3) << 2;
            *(float4*)&Xs[r][k4] = *(const float4*)(x + (size_t)(row0 + r) * CH + k0 + k4);
            int kk = t >> 4, c4 = (t & 15) << 2;
            *(float4*)&Ws[kk][c4] = *(const float4*)(w + (size_t)(k0 + kk) * (3 * CH) + col0 + c4);
        }
        __syncthreads();
        #pragma unroll
        for (int k4 = 0; k4 < 16; k4 += 4) {
            float4 xv[4], wv[4];
            #pragma unroll
            for (int i = 0; i < 4; i++) xv[i] = *(float4*)&Xs[ty * 4 + i][k4];
            #pragma unroll
            for (int kk = 0; kk < 4; kk++) wv[kk] = *(float4*)&Ws[k4 + kk][tx * 4];
            #pragma unroll
            for (int i = 0; i < 4; i++) {
                acc[i][0] += xv[i].x * wv[0].x + xv[i].y * wv[1].x + xv[i].z * wv[2].x + xv[i].w * wv[3].x;
                acc[i][1] += xv[i].x * wv[0].y + xv[i].y * wv[1].y + xv[i].z * wv[2].y + xv[i].w * wv[3].y;
                acc[i][2] += xv[i].x * wv[0].z + xv[i].y * wv[1].z + xv[i].z * wv[2].z + xv[i].w * wv[3].z;
                acc[i][3] += xv[i].x * wv[0].w + xv[i].y * wv[1].w + xv[i].z * wv[2].w + xv[i].w * wv[3].w;
            }
        }
        __syncthreads();
    }

    const int which = col0 >> 8;            // 0=q 1=k 2=v
    const int head  = (col0 & 255) >> 6;
    float* dst = (which == 0) ? g_q : (which == 1) ? g_k : g_v;
    const float qscale = (which == 0) ? 0.125f : 1.0f;   // hd^-0.5 = 64^-0.5

    #pragma unroll
    for (int i = 0; i < 4; i++) {
        int rowg = row0 + ty * 4 + i;
        int b = rowg >> 12;
        int n = rowg & (SEQ - 1);
        float4 v;
        v.x = __uint_as_float(f2tf32((acc[i][0] + bias[col0 + tx * 4 + 0]) * qscale));
        v.y = __uint_as_float(f2tf32((acc[i][1] + bias[col0 + tx * 4 + 1]) * qscale));
        v.z = __uint_as_float(f2tf32((acc[i][2] + bias[col0 + tx * 4 + 2]) * qscale));
        v.w = __uint_as_float(f2tf32((acc[i][3] + bias[col0 + tx * 4 + 3]) * qscale));
        *(float4*)(dst + ((size_t)(b * NHEAD + head) * SEQ + n) * HD + (tx << 2)) = v;
    }
}

// ---------------------------------------------------------------------------
// Kernel 2: flash attention, tf32 tensor-core (mma.sync m16n8k8).
// 128 threads (4 warps). Bq=64 (16 rows/warp), Bk=64, hd=64.
// Strides: Q/K/P = 68 (banks 4g+tig conflict-free), V = 72 (banks 8t+g).
// ---------------------------------------------------------------------------
#define QST 68
#define KST 68
#define VST 72
#define PST 68
#define ATT_SMEM ((64 * QST + 64 * KST + 64 * VST + 64 * PST) * sizeof(float))

__global__ __launch_bounds__(128)
void attn_kernel() {
    extern __shared__ float sm[];
    float* Qs = sm;
    float* Ks = Qs + 64 * QST;
    float* Vs = Ks + 64 * KST;
    float* Ps = Vs + 64 * VST;
    unsigned* Qsu = (unsigned*)Qs;
    unsigned* Ksu = (unsigned*)Ks;
    unsigned* Vsu = (unsigned*)Vs;
    unsigned* Psu = (unsigned*)Ps;

    const int t    = threadIdx.x;
    const int warp = t >> 5;
    const int lane = t & 31;
    const int g    = lane >> 2;     // groupID 0..7
    const int tig  = lane & 3;      // thread-in-group 0..3
    const int r0   = warp * 16;     // this warp's 16 query rows
    const int bh   = blockIdx.y;
    const int q0   = blockIdx.x << 6;

    const float* Qg = g_q + (size_t)bh * SEQ * HD + (size_t)q0 * HD;
    const float* Kg = g_k + (size_t)bh * SEQ * HD;
    const float* Vg = g_v + (size_t)bh * SEQ * HD;

    // Load Q tile (tf32-rounded already)
    #pragma unroll
    for (int i = 0; i < 8; i++) {
        int idx = t + 128 * i;
        int r = idx >> 4, c4 = (idx & 15) << 2;
        *(float4*)(Qs + r * QST + c4) = *(const float4*)(Qg + r * HD + c4);
    }

    float m0 = -1e30f, m1 = -1e30f, l0 = 0.0f, l1 = 0.0f;
    float oacc[8][4];
    #pragma unroll
    for (int nt = 0; nt < 8; nt++)
        #pragma unroll
        for (int j = 0; j < 4; j++) oacc[nt][j] = 0.0f;

    for (int kt = 0; kt < SEQ / 64; kt++) {
        __syncthreads();
        const float* Kt = Kg + (size_t)kt * 64 * HD;
        const float* Vt = Vg + (size_t)kt * 64 * HD;
        #pragma unroll
        for (int i = 0; i < 8; i++) {
            int idx = t + 128 * i;
            int r = idx >> 4, c4 = (idx & 15) << 2;
            *(float4*)(Ks + r * KST + c4) = *(const float4*)(Kt + r * HD + c4);
            *(float4*)(Vs + r * VST + c4) = *(const float4*)(Vt + r * HD + c4);
        }
        __syncthreads();

        // ---- S = Q K^T  (m16 x n64, k64) ----
        float sacc[8][4];
        #pragma unroll
        for (int nt = 0; nt < 8; nt++)
            #pragma unroll
            for (int j = 0; j < 4; j++) sacc[nt][j] = 0.0f;

        #pragma unroll
        for (int ks = 0; ks < 8; ks++) {
            const int d0 = ks * 8;
            unsigned a0 = Qsu[(r0 + g) * QST + d0 + tig];
            unsigned a1 = Qsu[(r0 + g + 8) * QST + d0 + tig];
            unsigned a2 = Qsu[(r0 + g) * QST + d0 + tig + 4];
            unsigned a3 = Qsu[(r0 + g + 8) * QST + d0 + tig + 4];
            #pragma unroll
            for (int nt = 0; nt < 8; nt++) {
                unsigned b0 = Ksu[(nt * 8 + g) * KST + d0 + tig];
                unsigned b1 = Ksu[(nt * 8 + g) * KST + d0 + tig + 4];
                mma_tf32(sacc[nt][0], sacc[nt][1], sacc[nt][2], sacc[nt][3],
                         a0, a1, a2, a3, b0, b1);
            }
        }

        // ---- online softmax on fragments ----
        float mx0 = -1e30f, mx1 = -1e30f;
        #pragma unroll
        for (int nt = 0; nt < 8; nt++) {
            mx0 = fmaxf(mx0, fmaxf(sacc[nt][0], sacc[nt][1]));
            mx1 = fmaxf(mx1, fmaxf(sacc[nt][2], sacc[nt][3]));
        }
        mx0 = fmaxf(mx0, __shfl_xor_sync(0xffffffffu, mx0, 1));
        mx0 = fmaxf(mx0, __shfl_xor_sync(0xffffffffu, mx0, 2));
        mx1 = fmaxf(mx1, __shfl_xor_sync(0xffffffffu, mx1, 1));
        mx1 = fmaxf(mx1, __shfl_xor_sync(0xffffffffu, mx1, 2));

        float mn0 = fmaxf(m0, mx0), mn1 = fmaxf(m1, mx1);
        float al0 = __expf(m0 - mn0), al1 = __expf(m1 - mn1);
        float rs0 = 0.0f, rs1 = 0.0f;
        #pragma unroll
        for (int nt = 0; nt < 8; nt++) {
            sacc[nt][0] = __expf(sacc[nt][0] - mn0);
            sacc[nt][1] = __expf(sacc[nt][1] - mn0);
            sacc[nt][2] = __expf(sacc[nt][2] - mn1);
            sacc[nt][3] = __expf(sacc[nt][3] - mn1);
            rs0 += sacc[nt][0] + sacc[nt][1];
            rs1 += sacc[nt][2] + sacc[nt][3];
        }
        rs0 += __shfl_xor_sync(0xffffffffu, rs0, 1);
        rs0 += __shfl_xor_sync(0xffffffffu, rs0, 2);
        rs1 += __shfl_xor_sync(0xffffffffu, rs1, 1);
        rs1 += __shfl_xor_sync(0xffffffffu, rs1, 2);
        m0 = mn0; m1 = mn1;
        l0 = l0 * al0 + rs0;
        l1 = l1 * al1 + rs1;
        #pragma unroll
        for (int nt = 0; nt < 8; nt++) {
            oacc[nt][0] *= al0; oacc[nt][1] *= al0;
            oacc[nt][2] *= al1; oacc[nt][3] *= al1;
        }

        // ---- stage P (tf32) — warp-private rows, no block sync needed ----
        #pragma unroll
        for (int nt = 0; nt < 8; nt++) {
            *(float2*)(Ps + (r0 + g) * PST + nt * 8 + 2 * tig) =
                make_float2(__uint_as_float(f2tf32(sacc[nt][0])),
                            __uint_as_float(f2tf32(sacc[nt][1])));
            *(float2*)(Ps + (r0 + g + 8) * PST + nt * 8 + 2 * tig) =
                make_float2(__uint_as_float(f2tf32(sacc[nt][2])),
                            __uint_as_float(f2tf32(sacc[nt][3])));
        }
        __syncwarp();

        // ---- O += P V  (m16 x n64, k64) ----
        #pragma unroll
        for (int ks = 0; ks < 8; ks++) {
            const int k0 = ks * 8;
            unsigned a0 = Psu[(r0 + g) * PST + k0 + tig];
            unsigned a1 = Psu[(r0 + g + 8) * PST + k0 + tig];
            unsigned a2 = Psu[(r0 + g) * PST + k0 + tig + 4];
            unsigned a3 = Psu[(r0 + g + 8) * PST + k0 + tig + 4];
            #pragma unroll
            for (int nt = 0; nt < 8; nt++) {
                unsigned b0 = Vsu[(k0 + tig) * VST + nt * 8 + g];
                unsigned b1 = Vsu[(k0 + tig + 4) * VST + nt * 8 + g];
                mma_tf32(oacc[nt][0], oacc[nt][1], oacc[nt][2], oacc[nt][3],
                         a0, a1, a2, a3, b0, b1);
            }
        }
    }

    float inv0 = 1.0f / l0, inv1 = 1.0f / l1;
    float* Og = g_o + (size_t)bh * SEQ * HD + (size_t)q0 * HD;
    #pragma unroll
    for (int nt = 0; nt < 8; nt++) {
        *(float2*)(Og + (r0 + g) * HD + nt * 8 + 2 * tig) =
            make_float2(oacc[nt][0] * inv0, oacc[nt][1] * inv0);
        *(float2*)(Og + (r0 + g + 8) * HD + nt * 8 + 2 * tig) =
            make_float2(oacc[nt][2] * inv1, oacc[nt][3] * inv1);
    }
}

// ---------------------------------------------------------------------------
// Kernel 3: output projection.  O[16384,256] @ W_out[256,256] + b_out -> out.
// ---------------------------------------------------------------------------
__global__ __launch_bounds__(256)
void proj_kernel(const float* __restrict__ w, const float* __restrict__ bias,
                 float* __restrict__ out) {
    __shared__ float Xs[64][16];
    __shared__ float Ws[16][64];
    const int t  = threadIdx.x;
    const int tx = t & 15, ty = t >> 4;
    const int row0 = blockIdx.y * 64;
    const int col0 = blockIdx.x * 64;
    const int b  = row0 >> 12;
    const int n0 = row0 & (SEQ - 1);

    float acc[4][4] = {};

    for (int k0 = 0; k0 < CH; k0 += 16) {
        const int h  = k0 >> 6;
        const int d0 = k0 & 63;
        {
            int r = t >> 2, k4 = (t & 3) << 2;
            const float* src = g_o + ((size_t)(b * NHEAD + h) * SEQ + n0 + r) * HD + d0 + k4;
            *(float4*)&Xs[r][k4] = *(const float4*)src;
            int kk = t >> 4, c4 = (t & 15) << 2;
            *(float4*)&Ws[kk][c4] = *(const float4*)(w + (size_t)(k0 + kk) * CH + col0 + c4);
        }
        __syncthreads();
        #pragma unroll
        for (int k4 = 0; k4 < 16; k4 += 4) {
            float4 xv[4], wv[4];
            #pragma unroll
            for (int i = 0; i < 4; i++) xv[i] = *(float4*)&Xs[ty * 4 + i][k4];
            #pragma unroll
            for (int kk = 0; kk < 4; kk++) wv[kk] = *(float4*)&Ws[k4 + kk][tx * 4];
            #pragma unroll
            for (int i = 0; i < 4; i++) {
                acc[i][0] += xv[i].x * wv[0].x + xv[i].y * wv[1].x + xv[i].z * wv[2].x + xv[i].w * wv[3].x;
                acc[i][1] += xv[i].x * wv[0].y + xv[i].y * wv[1].y + xv[i].z * wv[2].y + xv[i].w * wv[3].y;
                acc[i][2] += xv[i].x * wv[0].z + xv[i].y * wv[1].z + xv[i].z * wv[2].z + xv[i].w * wv[3].z;
                acc[i][3] += xv[i].x * wv[0].w + xv[i].y * wv[1].w + xv[i].z * wv[2].w + xv[i].w * wv[3].w;
            }
        }
        __syncthreads();
    }

    #pragma unroll
    for (int i = 0; i < 4; i++) {
        float4 v;
        v.x = acc[i][0] + bias[col0 + tx * 4 + 0];
        v.y = acc[i][1] + bias[col0 + tx * 4 + 1];
        v.z = acc[i][2] + bias[col0 + tx * 4 + 2];
        v.w = acc[i][3] + bias[col0 + tx * 4 + 3];
        *(float4*)(out + (size_t)(row0 + ty * 4 + i) * CH + col0 + (tx << 2)) = v;
    }
}

// ---------------------------------------------------------------------------
extern "C" void kernel_launch(void* const* d_in, const int* in_sizes, int n_in,
                              void* d_out, int out_size) {
    const float* x     = (const float*)d_in[0];
    const float* w_qkv = (const float*)d_in[1];
    const float* b_qkv = (const float*)d_in[2];
    const float* w_out = (const float*)d_in[3];
    const float* b_out = (const float*)d_in[4];
    float* out = (float*)d_out;

    qkv_kernel<<<dim3(12, NTOK / 64), 256>>>(x, w_qkv, b_qkv);

    cudaFuncSetAttribute(attn_kernel,
                         cudaFuncAttributeMaxDynamicSharedMemorySize,
                         (int)ATT_SMEM);
    attn_kernel<<<dim3(SEQ / 64, BATCH * NHEAD), 128, ATT_SMEM>>>();

    proj_kernel<<<dim3(CH / 64, NTOK / 64), 256>>>(w_out, b_out, out);
}

// round 3
// speedup vs baseline: 5.3230x; 1.4058x over previous
#include <cuda_runtime.h>

#define BATCH 4
#define NHEAD 4
#define SEQ   4096
#define HD    64
#define CH    256
#define NTOK  (BATCH * SEQ)   // 16384

#define QSCALE 0.1803368801111204f   // 64^-0.5 * log2(e)

// Scratch (device globals: allocation-free per harness rules)
__device__ float g_q[BATCH * NHEAD * SEQ * HD];
__device__ float g_k[BATCH * NHEAD * SEQ * HD];
__device__ float g_v[BATCH * NHEAD * SEQ * HD];
__device__ float g_o[BATCH * NHEAD * SEQ * HD];
__device__ float g_wqkt[3 * CH * CH];   // [768][256]  (n-major, tf32, q-scaled)
__device__ float g_bqk[3 * CH];         // q-scaled bias
__device__ float g_wot[CH * CH];        // [256][256]  (n-major, tf32)

// ---------------------------------------------------------------------------
// helpers
// ---------------------------------------------------------------------------
__device__ __forceinline__ float f2tf32f(float x) {
    unsigned r;
    asm("cvt.rna.tf32.f32 %0, %1;" : "=r"(r) : "f"(x));
    return __uint_as_float(r);
}

__device__ __forceinline__ void mma_tf32(float& c0, float& c1, float& c2, float& c3,
                                         unsigned a0, unsigned a1, unsigned a2, unsigned a3,
                                         unsigned b0, unsigned b1) {
    asm volatile(
        "mma.sync.aligned.m16n8k8.row.col.f32.tf32.tf32.f32 "
        "{%0,%1,%2,%3},{%4,%5,%6,%7},{%8,%9},{%0,%1,%2,%3};\n"
        : "+f"(c0), "+f"(c1), "+f"(c2), "+f"(c3)
        : "r"(a0), "r"(a1), "r"(a2), "r"(a3), "r"(b0), "r"(b1));
}

// ---------------------------------------------------------------------------
// Prep: weight transpose  src[K][N] -> dst[N][K], tf32-rounded, first qcols
// output-rows scaled by qs. 32x32 smem tiles, 32x8 threads.
// ---------------------------------------------------------------------------
__global__ void transpose_prep(const float* __restrict__ src, float* __restrict__ dst,
                               int K, int N, int qcols, float qs) {
    __shared__ float tile[32][33];
    const int n0 = blockIdx.x * 32;
    const int k0 = blockIdx.y * 32;
    const int tx = threadIdx.x, ty = threadIdx.y;
    #pragma unroll
    for (int j = 0; j < 32; j += 8)
        tile[ty + j][tx] = src[(size_t)(k0 + ty + j) * N + n0 + tx];
    __syncthreads();
    #pragma unroll
    for (int j = 0; j < 32; j += 8) {
        int n = n0 + ty + j;
        float v = tile[tx][ty + j];
        if (n < qcols) v *= qs;
        dst[(size_t)n * K + k0 + tx] = f2tf32f(v);
    }
}

__global__ void bias_prep(const float* __restrict__ b) {
    int i = blockIdx.x * 256 + threadIdx.x;
    if (i < 3 * CH) g_bqk[i] = b[i] * (i < CH ? QSCALE : 1.0f);
}

// ---------------------------------------------------------------------------
// Kernel 1: QKV projection, tf32 mma.  X[16384,256] @ Wt^T -> q/k/v scratch.
// CTA 128x64, 4 warps (m32 x n64 each), BK=32.
// ---------------------------------------------------------------------------
#define XST 36
__global__ __launch_bounds__(128)
void qkv_kernel(const float* __restrict__ x) {
    __shared__ float Xs[128 * XST];
    __shared__ float Wn[64 * XST];
    unsigned* Xsu = (unsigned*)Xs;
    unsigned* Wnu = (unsigned*)Wn;

    const int t    = threadIdx.x;
    const int warp = t >> 5;
    const int lane = t & 31;
    const int g    = lane >> 2;
    const int tig  = lane & 3;
    const int r0   = warp * 32;
    const int row0 = blockIdx.y * 128;
    const int col0 = blockIdx.x * 64;

    float acc[2][8][4];
    #pragma unroll
    for (int b = 0; b < 2; b++)
        #pragma unroll
        for (int nt = 0; nt < 8; nt++)
            #pragma unroll
            for (int j = 0; j < 4; j++) acc[b][nt][j] = 0.0f;

    for (int k0 = 0; k0 < CH; k0 += 32) {
        #pragma unroll
        for (int i = 0; i < 8; i++) {           // X: 128 rows x 32 cols
            int id = t + 128 * i;
            int r = id >> 3, c4 = (id & 7) << 2;
            float4 v = *(const float4*)(x + (size_t)(row0 + r) * CH + k0 + c4);
            v.x = f2tf32f(v.x); v.y = f2tf32f(v.y);
            v.z = f2tf32f(v.z); v.w = f2tf32f(v.w);
            *(float4*)(Xs + r * XST + c4) = v;
        }
        #pragma unroll
        for (int i = 0; i < 4; i++) {           // Wt: 64 n-rows x 32 k
            int id = t + 128 * i;
            int r = id >> 3, c4 = (id & 7) << 2;
            *(float4*)(Wn + r * XST + c4) =
                *(const float4*)(g_wqkt + (size_t)(col0 + r) * CH + k0 + c4);
        }
        __syncthreads();
        #pragma unroll
        for (int ks = 0; ks < 4; ks++) {
            const int d0 = ks * 8;
            unsigned a[2][4];
            #pragma unroll
            for (int b = 0; b < 2; b++) {
                a[b][0] = Xsu[(r0 + 16 * b + g) * XST + d0 + tig];
                a[b][1] = Xsu[(r0 + 16 * b + g + 8) * XST + d0 + tig];
                a[b][2] = Xsu[(r0 + 16 * b + g) * XST + d0 + tig + 4];
                a[b][3] = Xsu[(r0 + 16 * b + g + 8) * XST + d0 + tig + 4];
            }
            #pragma unroll
            for (int nt = 0; nt < 8; nt++) {
                unsigned b0 = Wnu[(nt * 8 + g) * XST + d0 + tig];
                unsigned b1 = Wnu[(nt * 8 + g) * XST + d0 + tig + 4];
                #pragma unroll
                for (int b = 0; b < 2; b++)
                    mma_tf32(acc[b][nt][0], acc[b][nt][1], acc[b][nt][2], acc[b][nt][3],
                             a[b][0], a[b][1], a[b][2], a[b][3], b0, b1);
            }
        }
        __syncthreads();
    }

    const int which = col0 >> 8;
    const int head  = (col0 & 255) >> 6;
    float* dst = (which == 0) ? g_q : (which == 1) ? g_k : g_v;

    #pragma unroll
    for (int b = 0; b < 2; b++)
        #pragma unroll
        for (int nt = 0; nt < 8; nt++) {
            int d = nt * 8 + 2 * tig;
            float2 bl = *(const float2*)(g_bqk + col0 + d);
            int row = row0 + r0 + 16 * b + g;
            int bb = row >> 12, n = row & (SEQ - 1);
            float2 v0 = make_float2(f2tf32f(acc[b][nt][0] + bl.x),
                                    f2tf32f(acc[b][nt][1] + bl.y));
            *(float2*)(dst + ((size_t)(bb * NHEAD + head) * SEQ + n) * HD + d) = v0;
            row += 8; bb = row >> 12; n = row & (SEQ - 1);
            float2 v1 = make_float2(f2tf32f(acc[b][nt][2] + bl.x),
                                    f2tf32f(acc[b][nt][3] + bl.y));
            *(float2*)(dst + ((size_t)(bb * NHEAD + head) * SEQ + n) * HD + d) = v1;
        }
}

// ---------------------------------------------------------------------------
// Kernel 2: flash attention, tf32 mma. Bq=128, Bk=64, 4 warps (m32 each).
// Q pre-scaled by 64^-0.5*log2e -> exp2 softmax.
// ---------------------------------------------------------------------------
#define QST 68
#define KST 68
#define VST 72
#define PST 68
#define ATT_SMEM ((128 * QST + 64 * KST + 64 * VST + 128 * PST) * sizeof(float))

__global__ __launch_bounds__(128)
void attn_kernel() {
    extern __shared__ float sm[];
    float* Qs = sm;
    float* Ks = Qs + 128 * QST;
    float* Vs = Ks + 64 * KST;
    float* Ps = Vs + 64 * VST;
    unsigned* Qsu = (unsigned*)Qs;
    unsigned* Ksu = (unsigned*)Ks;
    unsigned* Vsu = (unsigned*)Vs;
    unsigned* Psu = (unsigned*)Ps;

    const int t    = threadIdx.x;
    const int warp = t >> 5;
    const int lane = t & 31;
    const int g    = lane >> 2;
    const int tig  = lane & 3;
    const int r0   = warp * 32;
    const int bh   = blockIdx.y;
    const int q0   = blockIdx.x << 7;

    const float* Qg = g_q + (size_t)bh * SEQ * HD + (size_t)q0 * HD;
    const float* Kg = g_k + (size_t)bh * SEQ * HD;
    const float* Vg = g_v + (size_t)bh * SEQ * HD;

    #pragma unroll
    for (int i = 0; i < 16; i++) {
        int idx = t + 128 * i;
        int r = idx >> 4, c4 = (idx & 15) << 2;
        *(float4*)(Qs + r * QST + c4) = *(const float4*)(Qg + r * HD + c4);
    }

    float mm[2][2], ll[2][2];
    float oacc[2][8][4];
    #pragma unroll
    for (int b = 0; b < 2; b++) {
        mm[b][0] = mm[b][1] = -1e30f;
        ll[b][0] = ll[b][1] = 0.0f;
        #pragma unroll
        for (int nt = 0; nt < 8; nt++)
            #pragma unroll
            for (int j = 0; j < 4; j++) oacc[b][nt][j] = 0.0f;
    }

    for (int kt = 0; kt < SEQ / 64; kt++) {
        __syncthreads();
        const float* Kt = Kg + (size_t)kt * 64 * HD;
        const float* Vt = Vg + (size_t)kt * 64 * HD;
        #pragma unroll
        for (int i = 0; i < 8; i++) {
            int idx = t + 128 * i;
            int r = idx >> 4, c4 = (idx & 15) << 2;
            *(float4*)(Ks + r * KST + c4) = *(const float4*)(Kt + r * HD + c4);
            *(float4*)(Vs + r * VST + c4) = *(const float4*)(Vt + r * HD + c4);
        }
        __syncthreads();

        // ---- S = Q K^T ----
        float sacc[2][8][4];
        #pragma unroll
        for (int b = 0; b < 2; b++)
            #pragma unroll
            for (int nt = 0; nt < 8; nt++)
                #pragma unroll
                for (int j = 0; j < 4; j++) sacc[b][nt][j] = 0.0f;

        #pragma unroll
        for (int ks = 0; ks < 8; ks++) {
            const int d0 = ks * 8;
            unsigned a[2][4];
            #pragma unroll
            for (int b = 0; b < 2; b++) {
                a[b][0] = Qsu[(r0 + 16 * b + g) * QST + d0 + tig];
                a[b][1] = Qsu[(r0 + 16 * b + g + 8) * QST + d0 + tig];
                a[b][2] = Qsu[(r0 + 16 * b + g) * QST + d0 + tig + 4];
                a[b][3] = Qsu[(r0 + 16 * b + g + 8) * QST + d0 + tig + 4];
            }
            #pragma unroll
            for (int nt = 0; nt < 8; nt++) {
                unsigned b0 = Ksu[(nt * 8 + g) * KST + d0 + tig];
                unsigned b1 = Ksu[(nt * 8 + g) * KST + d0 + tig + 4];
                #pragma unroll
                for (int b = 0; b < 2; b++)
                    mma_tf32(sacc[b][nt][0], sacc[b][nt][1], sacc[b][nt][2], sacc[b][nt][3],
                             a[b][0], a[b][1], a[b][2], a[b][3], b0, b1);
            }
        }

        // ---- online softmax (base-2) ----
        #pragma unroll
        for (int b = 0; b < 2; b++) {
            float mx0 = -1e30f, mx1 = -1e30f;
            #pragma unroll
            for (int nt = 0; nt < 8; nt++) {
                mx0 = fmaxf(mx0, fmaxf(sacc[b][nt][0], sacc[b][nt][1]));
                mx1 = fmaxf(mx1, fmaxf(sacc[b][nt][2], sacc[b][nt][3]));
            }
            mx0 = fmaxf(mx0, __shfl_xor_sync(0xffffffffu, mx0, 1));
            mx0 = fmaxf(mx0, __shfl_xor_sync(0xffffffffu, mx0, 2));
            mx1 = fmaxf(mx1, __shfl_xor_sync(0xffffffffu, mx1, 1));
            mx1 = fmaxf(mx1, __shfl_xor_sync(0xffffffffu, mx1, 2));
            float mn0 = fmaxf(mm[b][0], mx0), mn1 = fmaxf(mm[b][1], mx1);
            float al0 = exp2f(mm[b][0] - mn0), al1 = exp2f(mm[b][1] - mn1);
            float rs0 = 0.0f, rs1 = 0.0f;
            #pragma unroll
            for (int nt = 0; nt < 8; nt++) {
                sacc[b][nt][0] = exp2f(sacc[b][nt][0] - mn0);
                sacc[b][nt][1] = exp2f(sacc[b][nt][1] - mn0);
                sacc[b][nt][2] = exp2f(sacc[b][nt][2] - mn1);
                sacc[b][nt][3] = exp2f(sacc[b][nt][3] - mn1);
                rs0 += sacc[b][nt][0] + sacc[b][nt][1];
                rs1 += sacc[b][nt][2] + sacc[b][nt][3];
            }
            rs0 += __shfl_xor_sync(0xffffffffu, rs0, 1);
            rs0 += __shfl_xor_sync(0xffffffffu, rs0, 2);
            rs1 += __shfl_xor_sync(0xffffffffu, rs1, 1);
            rs1 += __shfl_xor_sync(0xffffffffu, rs1, 2);
            mm[b][0] = mn0; mm[b][1] = mn1;
            ll[b][0] = ll[b][0] * al0 + rs0;
            ll[b][1] = ll[b][1] * al1 + rs1;
            #pragma unroll
            for (int nt = 0; nt < 8; nt++) {
                oacc[b][nt][0] *= al0; oacc[b][nt][1] *= al0;
                oacc[b][nt][2] *= al1; oacc[b][nt][3] *= al1;
            }
            // stage P (warp-private rows)
            #pragma unroll
            for (int nt = 0; nt < 8; nt++) {
                *(float2*)(Ps + (r0 + 16 * b + g) * PST + nt * 8 + 2 * tig) =
                    make_float2(f2tf32f(sacc[b][nt][0]), f2tf32f(sacc[b][nt][1]));
                *(float2*)(Ps + (r0 + 16 * b + g + 8) * PST + nt * 8 + 2 * tig) =
                    make_float2(f2tf32f(sacc[b][nt][2]), f2tf32f(sacc[b][nt][3]));
            }
        }
        __syncwarp();

        // ---- O += P V ----
        #pragma unroll
        for (int ks = 0; ks < 8; ks++) {
            const int k0 = ks * 8;
            unsigned a[2][4];
            #pragma unroll
            for (int b = 0; b < 2; b++) {
                a[b][0] = Psu[(r0 + 16 * b + g) * PST + k0 + tig];
                a[b][1] = Psu[(r0 + 16 * b + g + 8) * PST + k0 + tig];
                a[b][2] = Psu[(r0 + 16 * b + g) * PST + k0 + tig + 4];
                a[b][3] = Psu[(r0 + 16 * b + g + 8) * PST + k0 + tig + 4];
            }
            #pragma unroll
            for (int nt = 0; nt < 8; nt++) {
                unsigned b0 = Vsu[(k0 + tig) * VST + nt * 8 + g];
                unsigned b1 = Vsu[(k0 + tig + 4) * VST + nt * 8 + g];
                #pragma unroll
                for (int b = 0; b < 2; b++)
                    mma_tf32(oacc[b][nt][0], oacc[b][nt][1], oacc[b][nt][2], oacc[b][nt][3],
                             a[b][0], a[b][1], a[b][2], a[b][3], b0, b1);
            }
        }
    }

    float* Og = g_o + (size_t)bh * SEQ * HD + (size_t)q0 * HD;
    #pragma unroll
    for (int b = 0; b < 2; b++) {
        float inv0 = 1.0f / ll[b][0], inv1 = 1.0f / ll[b][1];
        #pragma unroll
        for (int nt = 0; nt < 8; nt++) {
            *(float2*)(Og + (r0 + 16 * b + g) * HD + nt * 8 + 2 * tig) =
                make_float2(oacc[b][nt][0] * inv0, oacc[b][nt][1] * inv0);
            *(float2*)(Og + (r0 + 16 * b + g + 8) * HD + nt * 8 + 2 * tig) =
                make_float2(oacc[b][nt][2] * inv1, oacc[b][nt][3] * inv1);
        }
    }
}

// ---------------------------------------------------------------------------
// Kernel 3: output projection, tf32 mma.  O[16384,256] @ Wot^T + b -> out.
// ---------------------------------------------------------------------------
__global__ __launch_bounds__(128)
void proj_kernel(const float* __restrict__ bias, float* __restrict__ out) {
    __shared__ float Xs[128 * XST];
    __shared__ float Wn[64 * XST];
    unsigned* Xsu = (unsigned*)Xs;
    unsigned* Wnu = (unsigned*)Wn;

    const int t    = threadIdx.x;
    const int warp = t >> 5;
    const int lane = t & 31;
    const int g    = lane >> 2;
    const int tig  = lane & 3;
    const int r0   = warp * 32;
    const int row0 = blockIdx.y * 128;
    const int col0 = blockIdx.x * 64;
    const int bb   = row0 >> 12;
    const int n0   = row0 & (SEQ - 1);

    float acc[2][8][4];
    #pragma unroll
    for (int b = 0; b < 2; b++)
        #pragma unroll
        for (int nt = 0; nt < 8; nt++)
            #pragma unroll
            for (int j = 0; j < 4; j++) acc[b][nt][j] = 0.0f;

    for (int k0 = 0; k0 < CH; k0 += 32) {
        const int h  = k0 >> 6;
        const int d0 = k0 & 63;
        #pragma unroll
        for (int i = 0; i < 8; i++) {
            int id = t + 128 * i;
            int r = id >> 3, c4 = (id & 7) << 2;
            float4 v = *(const float4*)(g_o +
                ((size_t)(bb * NHEAD + h) * SEQ + n0 + r) * HD + d0 + c4);
            v.x = f2tf32f(v.x); v.y = f2tf32f(v.y);
            v.z = f2tf32f(v.z); v.w = f2tf32f(v.w);
            *(float4*)(Xs + r * XST + c4) = v;
        }
        #pragma unroll
        for (int i = 0; i < 4; i++) {
            int id = t + 128 * i;
            int r = id >> 3, c4 = (id & 7) << 2;
            *(float4*)(Wn + r * XST + c4) =
                *(const float4*)(g_wot + (size_t)(col0 + r) * CH + k0 + c4);
        }
        __syncthreads();
        #pragma unroll
        for (int ks = 0; ks < 4; ks++) {
            const int d8 = ks * 8;
            unsigned a[2][4];
            #pragma unroll
            for (int b = 0; b < 2; b++) {
                a[b][0] = Xsu[(r0 + 16 * b + g) * XST + d8 + tig];
                a[b][1] = Xsu[(r0 + 16 * b + g + 8) * XST + d8 + tig];
                a[b][2] = Xsu[(r0 + 16 * b + g) * XST + d8 + tig + 4];
                a[b][3] = Xsu[(r0 + 16 * b + g + 8) * XST + d8 + tig + 4];
            }
            #pragma unroll
            for (int nt = 0; nt < 8; nt++) {
                unsigned b0 = Wnu[(nt * 8 + g) * XST + d8 + tig];
                unsigned b1 = Wnu[(nt * 8 + g) * XST + d8 + tig + 4];
                #pragma unroll
                for (int b = 0; b < 2; b++)
                    mma_tf32(acc[b][nt][0], acc[b][nt][1], acc[b][nt][2], acc[b][nt][3],
                             a[b][0], a[b][1], a[b][2], a[b][3], b0, b1);
            }
        }
        __syncthreads();
    }

    #pragma unroll
    for (int b = 0; b < 2; b++)
        #pragma unroll
        for (int nt = 0; nt < 8; nt++) {
            int d = nt * 8 + 2 * tig;
            float2 bl = *(const float2*)(bias + col0 + d);
            int row = row0 + r0 + 16 * b + g;
            *(float2*)(out + (size_t)row * CH + col0 + d) =
                make_float2(acc[b][nt][0] + bl.x, acc[b][nt][1] + bl.y);
            *(float2*)(out + (size_t)(row + 8) * CH + col0 + d) =
                make_float2(acc[b][nt][2] + bl.x, acc[b][nt][3] + bl.y);
        }
}

// ---------------------------------------------------------------------------
extern "C" void kernel_launch(void* const* d_in, const int* in_sizes, int n_in,
                              void* d_out, int out_size) {
    const float* x     = (const float*)d_in[0];
    const float* w_qkv = (const float*)d_in[1];
    const float* b_qkv = (const float*)d_in[2];
    const float* w_out = (const float*)d_in[3];
    const float* b_out = (const float*)d_in[4];
    float* out = (float*)d_out;

    float* wqkt; cudaGetSymbolAddress((void**)&wqkt, g_wqkt);
    float* wot;  cudaGetSymbolAddress((void**)&wot,  g_wot);

    transpose_prep<<<dim3(3 * CH / 32, CH / 32), dim3(32, 8)>>>(
        w_qkv, wqkt, CH, 3 * CH, CH, QSCALE);
    transpose_prep<<<dim3(CH / 32, CH / 32), dim3(32, 8)>>>(
        w_out, wot, CH, CH, 0, 1.0f);
    bias_prep<<<3, 256>>>(b_qkv);

    qkv_kernel<<<dim3(12, NTOK / 128), 128>>>(x);

    cudaFuncSetAttribute(attn_kernel,
                         cudaFuncAttributeMaxDynamicSharedMemorySize,
                         (int)ATT_SMEM);
    attn_kernel<<<dim3(SEQ / 128, BATCH * NHEAD), 128, ATT_SMEM>>>();

    proj_kernel<<<dim3(CH / 64, NTOK / 128), 128>>>(b_out, out);
}

// round 4
// speedup vs baseline: 5.5923x; 1.0506x over previous
#include <cuda_runtime.h>
#include <cstdint>

#define BATCH 4
#define NHEAD 4
#define SEQ   4096
#define HD    64
#define CH    256
#define NTOK  (BATCH * SEQ)   // 16384

#define QSCALE 0.1803368801111204f   // 64^-0.5 * log2(e)

// Scratch (device globals: allocation-free per harness rules)
__device__ float g_q[BATCH * NHEAD * SEQ * HD];
__device__ float g_k[BATCH * NHEAD * SEQ * HD];
__device__ float g_v[BATCH * NHEAD * SEQ * HD];
__device__ float g_o[BATCH * NHEAD * SEQ * HD];
__device__ float g_wqkt[3 * CH * CH];   // [768][256]  (n-major, tf32, q-scaled)
__device__ float g_bqk[3 * CH];         // q-scaled bias
__device__ float g_wot[CH * CH];        // [256][256]  (n-major, tf32)

// ---------------------------------------------------------------------------
// helpers
// ---------------------------------------------------------------------------
__device__ __forceinline__ float f2tf32f(float x) {
    unsigned r;
    asm("cvt.rna.tf32.f32 %0, %1;" : "=r"(r) : "f"(x));
    return __uint_as_float(r);
}

__device__ __forceinline__ void mma_tf32(float& c0, float& c1, float& c2, float& c3,
                                         unsigned a0, unsigned a1, unsigned a2, unsigned a3,
                                         unsigned b0, unsigned b1) {
    asm volatile(
        "mma.sync.aligned.m16n8k8.row.col.f32.tf32.tf32.f32 "
        "{%0,%1,%2,%3},{%4,%5,%6,%7},{%8,%9},{%0,%1,%2,%3};\n"
        : "+f"(c0), "+f"(c1), "+f"(c2), "+f"(c3)
        : "r"(a0), "r"(a1), "r"(a2), "r"(a3), "r"(b0), "r"(b1));
}

__device__ __forceinline__ void cpa16(uint32_t dst, const void* src) {
    asm volatile("cp.async.cg.shared.global [%0], [%1], 16;\n" :: "r"(dst), "l"(src));
}
__device__ __forceinline__ void cpa_commit() {
    asm volatile("cp.async.commit_group;\n");
}
__device__ __forceinline__ void cpa_wait1() {
    asm volatile("cp.async.wait_group 1;\n");
}

// ---------------------------------------------------------------------------
// Prep: weight transpose  src[K][N] -> dst[N][K], tf32-rounded, first qcols
// output-rows scaled by qs.
// ---------------------------------------------------------------------------
__global__ void transpose_prep(const float* __restrict__ src, float* __restrict__ dst,
                               int K, int N, int qcols, float qs) {
    __shared__ float tile[32][33];
    const int n0 = blockIdx.x * 32;
    const int k0 = blockIdx.y * 32;
    const int tx = threadIdx.x, ty = threadIdx.y;
    #pragma unroll
    for (int j = 0; j < 32; j += 8)
        tile[ty + j][tx] = src[(size_t)(k0 + ty + j) * N + n0 + tx];
    __syncthreads();
    #pragma unroll
    for (int j = 0; j < 32; j += 8) {
        int n = n0 + ty + j;
        float v = tile[tx][ty + j];
        if (n < qcols) v *= qs;
        dst[(size_t)n * K + k0 + tx] = f2tf32f(v);
    }
}

__global__ void bias_prep(const float* __restrict__ b) {
    int i = blockIdx.x * 256 + threadIdx.x;
    if (i < 3 * CH) g_bqk[i] = b[i] * (i < CH ? QSCALE : 1.0f);
}

// ---------------------------------------------------------------------------
// Kernel 1: QKV projection, tf32 mma.  X[16384,256] @ Wt^T -> q/k/v scratch.
// ---------------------------------------------------------------------------
#define XST 36
__global__ __launch_bounds__(128)
void qkv_kernel(const float* __restrict__ x) {
    __shared__ float Xs[128 * XST];
    __shared__ float Wn[64 * XST];
    unsigned* Xsu = (unsigned*)Xs;
    unsigned* Wnu = (unsigned*)Wn;

    const int t    = threadIdx.x;
    const int warp = t >> 5;
    const int lane = t & 31;
    const int g    = lane >> 2;
    const int tig  = lane & 3;
    const int r0   = warp * 32;
    const int row0 = blockIdx.y * 128;
    const int col0 = blockIdx.x * 64;

    float acc[2][8][4];
    #pragma unroll
    for (int b = 0; b < 2; b++)
        #pragma unroll
        for (int nt = 0; nt < 8; nt++)
            #pragma unroll
            for (int j = 0; j < 4; j++) acc[b][nt][j] = 0.0f;

    for (int k0 = 0; k0 < CH; k0 += 32) {
        #pragma unroll
        for (int i = 0; i < 8; i++) {
            int id = t + 128 * i;
            int r = id >> 3, c4 = (id & 7) << 2;
            float4 v = *(const float4*)(x + (size_t)(row0 + r) * CH + k0 + c4);
            v.x = f2tf32f(v.x); v.y = f2tf32f(v.y);
            v.z = f2tf32f(v.z); v.w = f2tf32f(v.w);
            *(float4*)(Xs + r * XST + c4) = v;
        }
        #pragma unroll
        for (int i = 0; i < 4; i++) {
            int id = t + 128 * i;
            int r = id >> 3, c4 = (id & 7) << 2;
            *(float4*)(Wn + r * XST + c4) =
                *(const float4*)(g_wqkt + (size_t)(col0 + r) * CH + k0 + c4);
        }
        __syncthreads();
        #pragma unroll
        for (int ks = 0; ks < 4; ks++) {
            const int d0 = ks * 8;
            unsigned a[2][4];
            #pragma unroll
            for (int b = 0; b < 2; b++) {
                a[b][0] = Xsu[(r0 + 16 * b + g) * XST + d0 + tig];
                a[b][1] = Xsu[(r0 + 16 * b + g + 8) * XST + d0 + tig];
                a[b][2] = Xsu[(r0 + 16 * b + g) * XST + d0 + tig + 4];
                a[b][3] = Xsu[(r0 + 16 * b + g + 8) * XST + d0 + tig + 4];
            }
            #pragma unroll
            for (int nt = 0; nt < 8; nt++) {
                unsigned b0 = Wnu[(nt * 8 + g) * XST + d0 + tig];
                unsigned b1 = Wnu[(nt * 8 + g) * XST + d0 + tig + 4];
                #pragma unroll
                for (int b = 0; b < 2; b++)
                    mma_tf32(acc[b][nt][0], acc[b][nt][1], acc[b][nt][2], acc[b][nt][3],
                             a[b][0], a[b][1], a[b][2], a[b][3], b0, b1);
            }
        }
        __syncthreads();
    }

    const int which = col0 >> 8;
    const int head  = (col0 & 255) >> 6;
    float* dst = (which == 0) ? g_q : (which == 1) ? g_k : g_v;

    #pragma unroll
    for (int b = 0; b < 2; b++)
        #pragma unroll
        for (int nt = 0; nt < 8; nt++) {
            int d = nt * 8 + 2 * tig;
            float2 bl = *(const float2*)(g_bqk + col0 + d);
            int row = row0 + r0 + 16 * b + g;
            int bb = row >> 12, n = row & (SEQ - 1);
            float2 v0 = make_float2(f2tf32f(acc[b][nt][0] + bl.x),
                                    f2tf32f(acc[b][nt][1] + bl.y));
            *(float2*)(dst + ((size_t)(bb * NHEAD + head) * SEQ + n) * HD + d) = v0;
            row += 8; bb = row >> 12; n = row & (SEQ - 1);
            float2 v1 = make_float2(f2tf32f(acc[b][nt][2] + bl.x),
                                    f2tf32f(acc[b][nt][3] + bl.y));
            *(float2*)(dst + ((size_t)(bb * NHEAD + head) * SEQ + n) * HD + d) = v1;
        }
}

// ---------------------------------------------------------------------------
// Kernel 2: flash attention, tf32 mma, cp.async 2-stage pipeline.
// Bq=256 (8 warps, m32/warp), Bk=64, double-buffered K/V.
// ---------------------------------------------------------------------------
#define BQ  256
#define QST 68
#define KST 68
#define VST 72
#define PST 68
#define NKT (SEQ / 64)
#define ATT_SMEM ((BQ * QST + 2 * 64 * KST + 2 * 64 * VST + BQ * PST) * sizeof(float))

__global__ __launch_bounds__(256)
void attn_kernel() {
    extern __shared__ float sm[];
    float* Qs  = sm;
    float* Ks0 = Qs + BQ * QST;              // two K buffers, contiguous
    float* Vs0 = Ks0 + 2 * 64 * KST;         // two V buffers, contiguous
    float* Ps  = Vs0 + 2 * 64 * VST;
    unsigned* Qsu = (unsigned*)Qs;
    unsigned* Psu = (unsigned*)Ps;

    const uint32_t sQ = (uint32_t)__cvta_generic_to_shared(Qs);
    const uint32_t sK = (uint32_t)__cvta_generic_to_shared(Ks0);
    const uint32_t sV = (uint32_t)__cvta_generic_to_shared(Vs0);

    const int t    = threadIdx.x;
    const int warp = t >> 5;
    const int lane = t & 31;
    const int g    = lane >> 2;
    const int tig  = lane & 3;
    const int r0   = warp * 32;
    const int bh   = blockIdx.y;
    const int q0   = blockIdx.x << 8;

    const float* Qg = g_q + (size_t)bh * SEQ * HD + (size_t)q0 * HD;
    const float* Kg = g_k + (size_t)bh * SEQ * HD;
    const float* Vg = g_v + (size_t)bh * SEQ * HD;

    // prologue: group0 = Q + K0 + V0 ; group1 = K1 + V1
    #pragma unroll
    for (int i = 0; i < 16; i++) {      // Q: 256 rows x 64 cols
        int idx = t + 256 * i;
        int r = idx >> 4, c4 = (idx & 15) << 2;
        cpa16(sQ + (r * QST + c4) * 4, Qg + r * HD + c4);
    }
    #pragma unroll
    for (int i = 0; i < 4; i++) {       // K0 / V0
        int idx = t + 256 * i;
        int r = idx >> 4, c4 = (idx & 15) << 2;
        cpa16(sK + (r * KST + c4) * 4, Kg + r * HD + c4);
        cpa16(sV + (r * VST + c4) * 4, Vg + r * HD + c4);
    }
    cpa_commit();
    #pragma unroll
    for (int i = 0; i < 4; i++) {       // K1 / V1
        int idx = t + 256 * i;
        int r = idx >> 4, c4 = (idx & 15) << 2;
        cpa16(sK + ((64 + r) * KST + c4) * 4, Kg + (64 + r) * HD + c4);
        cpa16(sV + ((64 + r) * VST + c4) * 4, Vg + (64 + r) * HD + c4);
    }
    cpa_commit();

    float mm[2][2], ll[2][2];
    float oacc[2][8][4];
    #pragma unroll
    for (int b = 0; b < 2; b++) {
        mm[b][0] = mm[b][1] = -1e30f;
        ll[b][0] = ll[b][1] = 0.0f;
        #pragma unroll
        for (int nt = 0; nt < 8; nt++)
            #pragma unroll
            for (int j = 0; j < 4; j++) oacc[b][nt][j] = 0.0f;
    }

    for (int kt = 0; kt < NKT; kt++) {
        const int buf = kt & 1;
        unsigned* Ksu = (unsigned*)(Ks0 + buf * 64 * KST);
        unsigned* Vsu = (unsigned*)(Vs0 + buf * 64 * VST);

        cpa_wait1();
        __syncthreads();

        // ---- S = Q K^T ----
        float sacc[2][8][4];
        #pragma unroll
        for (int b = 0; b < 2; b++)
            #pragma unroll
            for (int nt = 0; nt < 8; nt++)
                #pragma unroll
                for (int j = 0; j < 4; j++) sacc[b][nt][j] = 0.0f;

        #pragma unroll
        for (int ks = 0; ks < 8; ks++) {
            const int d0 = ks * 8;
            unsigned a[2][4];
            #pragma unroll
            for (int b = 0; b < 2; b++) {
                a[b][0] = Qsu[(r0 + 16 * b + g) * QST + d0 + tig];
                a[b][1] = Qsu[(r0 + 16 * b + g + 8) * QST + d0 + tig];
                a[b][2] = Qsu[(r0 + 16 * b + g) * QST + d0 + tig + 4];
                a[b][3] = Qsu[(r0 + 16 * b + g + 8) * QST + d0 + tig + 4];
            }
            #pragma unroll
            for (int nt = 0; nt < 8; nt++) {
                unsigned b0 = Ksu[(nt * 8 + g) * KST + d0 + tig];
                unsigned b1 = Ksu[(nt * 8 + g) * KST + d0 + tig + 4];
                #pragma unroll
                for (int b = 0; b < 2; b++)
                    mma_tf32(sacc[b][nt][0], sacc[b][nt][1], sacc[b][nt][2], sacc[b][nt][3],
                             a[b][0], a[b][1], a[b][2], a[b][3], b0, b1);
            }
        }

        // ---- online softmax (base-2) + stage P ----
        #pragma unroll
        for (int b = 0; b < 2; b++) {
            float mx0 = -1e30f, mx1 = -1e30f;
            #pragma unroll
            for (int nt = 0; nt < 8; nt++) {
                mx0 = fmaxf(mx0, fmaxf(sacc[b][nt][0], sacc[b][nt][1]));
                mx1 = fmaxf(mx1, fmaxf(sacc[b][nt][2], sacc[b][nt][3]));
            }
            mx0 = fmaxf(mx0, __shfl_xor_sync(0xffffffffu, mx0, 1));
            mx0 = fmaxf(mx0, __shfl_xor_sync(0xffffffffu, mx0, 2));
            mx1 = fmaxf(mx1, __shfl_xor_sync(0xffffffffu, mx1, 1));
            mx1 = fmaxf(mx1, __shfl_xor_sync(0xffffffffu, mx1, 2));
            float mn0 = fmaxf(mm[b][0], mx0), mn1 = fmaxf(mm[b][1], mx1);
            float al0 = exp2f(mm[b][0] - mn0), al1 = exp2f(mm[b][1] - mn1);
            float rs0 = 0.0f, rs1 = 0.0f;
            #pragma unroll
            for (int nt = 0; nt < 8; nt++) {
                sacc[b][nt][0] = exp2f(sacc[b][nt][0] - mn0);
                sacc[b][nt][1] = exp2f(sacc[b][nt][1] - mn0);
                sacc[b][nt][2] = exp2f(sacc[b][nt][2] - mn1);
                sacc[b][nt][3] = exp2f(sacc[b][nt][3] - mn1);
                rs0 += sacc[b][nt][0] + sacc[b][nt][1];
                rs1 += sacc[b][nt][2] + sacc[b][nt][3];
            }
            rs0 += __shfl_xor_sync(0xffffffffu, rs0, 1);
            rs0 += __shfl_xor_sync(0xffffffffu, rs0, 2);
            rs1 += __shfl_xor_sync(0xffffffffu, rs1, 1);
            rs1 += __shfl_xor_sync(0xffffffffu, rs1, 2);
            mm[b][0] = mn0; mm[b][1] = mn1;
            ll[b][0] = ll[b][0] * al0 + rs0;
            ll[b][1] = ll[b][1] * al1 + rs1;
            #pragma unroll
            for (int nt = 0; nt < 8; nt++) {
                oacc[b][nt][0] *= al0; oacc[b][nt][1] *= al0;
                oacc[b][nt][2] *= al1; oacc[b][nt][3] *= al1;
            }
            #pragma unroll
            for (int nt = 0; nt < 8; nt++) {
                *(float2*)(Ps + (r0 + 16 * b + g) * PST + nt * 8 + 2 * tig) =
                    make_float2(f2tf32f(sacc[b][nt][0]), f2tf32f(sacc[b][nt][1]));
                *(float2*)(Ps + (r0 + 16 * b + g + 8) * PST + nt * 8 + 2 * tig) =
                    make_float2(f2tf32f(sacc[b][nt][2]), f2tf32f(sacc[b][nt][3]));
            }
        }
        __syncwarp();

        // ---- O += P V ----
        #pragma unroll
        for (int ks = 0; ks < 8; ks++) {
            const int k0 = ks * 8;
            unsigned a[2][4];
            #pragma unroll
            for (int b = 0; b < 2; b++) {
                a[b][0] = Psu[(r0 + 16 * b + g) * PST + k0 + tig];
                a[b][1] = Psu[(r0 + 16 * b + g + 8) * PST + k0 + tig];
                a[b][2] = Psu[(r0 + 16 * b + g) * PST + k0 + tig + 4];
                a[b][3] = Psu[(r0 + 16 * b + g + 8) * PST + k0 + tig + 4];
            }
            #pragma unroll
            for (int nt = 0; nt < 8; nt++) {
                unsigned b0 = Vsu[(k0 + tig) * VST + nt * 8 + g];
                unsigned b1 = Vsu[(k0 + tig + 4) * VST + nt * 8 + g];
                #pragma unroll
                for (int b = 0; b < 2; b++)
                    mma_tf32(oacc[b][nt][0], oacc[b][nt][1], oacc[b][nt][2], oacc[b][nt][3],
                             a[b][0], a[b][1], a[b][2], a[b][3], b0, b1);
            }
        }

        __syncthreads();   // all warps done with buf before reissue
        if (kt + 2 < NKT) {
            const float* Kt = Kg + (size_t)(kt + 2) * 64 * HD;
            const float* Vt = Vg + (size_t)(kt + 2) * 64 * HD;
            #pragma unroll
            for (int i = 0; i < 4; i++) {
                int idx = t + 256 * i;
                int r = idx >> 4, c4 = (idx & 15) << 2;
                cpa16(sK + ((buf * 64 + r) * KST + c4) * 4, Kt + r * HD + c4);
                cpa16(sV + ((buf * 64 + r) * VST + c4) * 4, Vt + r * HD + c4);
            }
        }
        cpa_commit();
    }

    float* Og = g_o + (size_t)bh * SEQ * HD + (size_t)q0 * HD;
    #pragma unroll
    for (int b = 0; b < 2; b++) {
        float inv0 = 1.0f / ll[b][0], inv1 = 1.0f / ll[b][1];
        #pragma unroll
        for (int nt = 0; nt < 8; nt++) {
            *(float2*)(Og + (r0 + 16 * b + g) * HD + nt * 8 + 2 * tig) =
                make_float2(oacc[b][nt][0] * inv0, oacc[b][nt][1] * inv0);
            *(float2*)(Og + (r0 + 16 * b + g + 8) * HD + nt * 8 + 2 * tig) =
                make_float2(oacc[b][nt][2] * inv1, oacc[b][nt][3] * inv1);
        }
    }
}

// ---------------------------------------------------------------------------
// Kernel 3: output projection, tf32 mma.
// ---------------------------------------------------------------------------
__global__ __launch_bounds__(128)
void proj_kernel(const float* __restrict__ bias, float* __restrict__ out) {
    __shared__ float Xs[128 * XST];
    __shared__ float Wn[64 * XST];
    unsigned* Xsu = (unsigned*)Xs;
    unsigned* Wnu = (unsigned*)Wn;

    const int t    = threadIdx.x;
    const int warp = t >> 5;
    const int lane = t & 31;
    const int g    = lane >> 2;
    const int tig  = lane & 3;
    const int r0   = warp * 32;
    const int row0 = blockIdx.y * 128;
    const int col0 = blockIdx.x * 64;
    const int bb   = row0 >> 12;
    const int n0   = row0 & (SEQ - 1);

    float acc[2][8][4];
    #pragma unroll
    for (int b = 0; b < 2; b++)
        #pragma unroll
        for (int nt = 0; nt < 8; nt++)
            #pragma unroll
            for (int j = 0; j < 4; j++) acc[b][nt][j] = 0.0f;

    for (int k0 = 0; k0 < CH; k0 += 32) {
        const int h  = k0 >> 6;
        const int d0 = k0 & 63;
        #pragma unroll
        for (int i = 0; i < 8; i++) {
            int id = t + 128 * i;
            int r = id >> 3, c4 = (id & 7) << 2;
            float4 v = *(const float4*)(g_o +
                ((size_t)(bb * NHEAD + h) * SEQ + n0 + r) * HD + d0 + c4);
            v.x = f2tf32f(v.x); v.y = f2tf32f(v.y);
            v.z = f2tf32f(v.z); v.w = f2tf32f(v.w);
            *(float4*)(Xs + r * XST + c4) = v;
        }
        #pragma unroll
        for (int i = 0; i < 4; i++) {
            int id = t + 128 * i;
            int r = id >> 3, c4 = (id & 7) << 2;
            *(float4*)(Wn + r * XST + c4) =
                *(const float4*)(g_wot + (size_t)(col0 + r) * CH + k0 + c4);
        }
        __syncthreads();
        #pragma unroll
        for (int ks = 0; ks < 4; ks++) {
            const int d8 = ks * 8;
            unsigned a[2][4];
            #pragma unroll
            for (int b = 0; b < 2; b++) {
                a[b][0] = Xsu[(r0 + 16 * b + g) * XST + d8 + tig];
                a[b][1] = Xsu[(r0 + 16 * b + g + 8) * XST + d8 + tig];
                a[b][2] = Xsu[(r0 + 16 * b + g) * XST + d8 + tig + 4];
                a[b][3] = Xsu[(r0 + 16 * b + g + 8) * XST + d8 + tig + 4];
            }
            #pragma unroll
            for (int nt = 0; nt < 8; nt++) {
                unsigned b0 = Wnu[(nt * 8 + g) * XST + d8 + tig];
                unsigned b1 = Wnu[(nt * 8 + g) * XST + d8 + tig + 4];
                #pragma unroll
                for (int b = 0; b < 2; b++)
                    mma_tf32(acc[b][nt][0], acc[b][nt][1], acc[b][nt][2], acc[b][nt][3],
                             a[b][0], a[b][1], a[b][2], a[b][3], b0, b1);
            }
        }
        __syncthreads();
    }

    #pragma unroll
    for (int b = 0; b < 2; b++)
        #pragma unroll
        for (int nt = 0; nt < 8; nt++) {
            int d = nt * 8 + 2 * tig;
            float2 bl = *(const float2*)(bias + col0 + d);
            int row = row0 + r0 + 16 * b + g;
            *(float2*)(out + (size_t)row * CH + col0 + d) =
                make_float2(acc[b][nt][0] + bl.x, acc[b][nt][1] + bl.y);
            *(float2*)(out + (size_t)(row + 8) * CH + col0 + d) =
                make_float2(acc[b][nt][2] + bl.x, acc[b][nt][3] + bl.y);
        }
}

// ---------------------------------------------------------------------------
extern "C" void kernel_launch(void* const* d_in, const int* in_sizes, int n_in,
                              void* d_out, int out_size) {
    const float* x     = (const float*)d_in[0];
    const float* w_qkv = (const float*)d_in[1];
    const float* b_qkv = (const float*)d_in[2];
    const float* w_out = (const float*)d_in[3];
    const float* b_out = (const float*)d_in[4];
    float* out = (float*)d_out;

    float* wqkt; cudaGetSymbolAddress((void**)&wqkt, g_wqkt);
    float* wot;  cudaGetSymbolAddress((void**)&wot,  g_wot);

    transpose_prep<<<dim3(3 * CH / 32, CH / 32), dim3(32, 8)>>>(
        w_qkv, wqkt, CH, 3 * CH, CH, QSCALE);
    transpose_prep<<<dim3(CH / 32, CH / 32), dim3(32, 8)>>>(
        w_out, wot, CH, CH, 0, 1.0f);
    bias_prep<<<3, 256>>>(b_qkv);

    qkv_kernel<<<dim3(12, NTOK / 128), 128>>>(x);

    cudaFuncSetAttribute(attn_kernel,
                         cudaFuncAttributeMaxDynamicSharedMemorySize,
                         (int)ATT_SMEM);
    attn_kernel<<<dim3(SEQ / BQ, BATCH * NHEAD), 256, ATT_SMEM>>>();

    proj_kernel<<<dim3(CH / 64, NTOK / 128), 128>>>(b_out, out);
}